// round 2
// baseline (speedup 1.0000x reference)
#include <cuda_runtime.h>
#include <cuda_bf16.h>
#include <math.h>
#include <float.h>

// ============================================================================
// VectorQuantizer: inputs (32768 x 256) fp32, codebook (256 x 1024) fp32.
// out = [ ste(32768*256) , perplexity, codebook_loss, commitment_loss ]
//
// dist(n,k) = |x_n|^2 - 2 x_n . c_k + |c_k|^2 ; argmin over k.
// |x|^2 is row-constant -> dropped from argmin. quantized row = c_{k*}.
// ============================================================================

#define D_DIM      256
#define K_CODES    1024
#define BM         64
#define BK         64
#define BD         16
#define THREADS    256
#define AS_STRIDE  258   // pad to kill 2-way bank conflicts on row-major A reads

__device__ float g_cT[K_CODES * D_DIM];    // codebook transposed [K][D]
__device__ float g_cnorm[K_CODES];         // |c_k|^2
__device__ int   g_counts[K_CODES];        // histogram
__device__ float g_sumsq;                  // sum (q - x)^2

// Dynamic smem bytes for main kernel
#define SMEM_MAIN ((BM * AS_STRIDE + BD * BK + BM * 16 + BM * 16) * 4)

// ---------------------------------------------------------------------------
__global__ void k_init() {
    int t = threadIdx.x;
    if (t < K_CODES) g_counts[t] = 0;
    if (t == 0) g_sumsq = 0.0f;
}

// cnorm[k] = sum_d codebook[d*K + k]^2 ; consecutive threads -> consecutive k
__global__ void k_cnorm(const float* __restrict__ cb) {
    int k = blockIdx.x * blockDim.x + threadIdx.x;
    float s = 0.0f;
    #pragma unroll 8
    for (int d = 0; d < D_DIM; d++) {
        float v = cb[d * K_CODES + k];
        s += v * v;
    }
    g_cnorm[k] = s;
}

// transpose codebook (D x K) -> cT (K x D), 32x32 tiles
__global__ void k_transpose(const float* __restrict__ cb) {
    __shared__ float t[32][33];
    int k = blockIdx.x * 32 + threadIdx.x;
    int d = blockIdx.y * 32 + threadIdx.y;
    t[threadIdx.y][threadIdx.x] = cb[d * K_CODES + k];
    __syncthreads();
    int ko = blockIdx.x * 32 + threadIdx.y;
    int do_ = blockIdx.y * 32 + threadIdx.x;
    g_cT[ko * D_DIM + do_] = t[threadIdx.x][threadIdx.y];
}

// ---------------------------------------------------------------------------
// Main fused kernel: GEMM (-2 x.c) + argmin + quantized write + loss partials
// Block: 256 threads, 64 rows. Grid: rows/64.
// ---------------------------------------------------------------------------
__global__ __launch_bounds__(THREADS, 2)
void k_main(const float* __restrict__ inputs,
            const float* __restrict__ cb,
            float* __restrict__ out) {
    extern __shared__ float smem[];
    float* As   = smem;                                // [BM][AS_STRIDE]
    float* Bs   = As + BM * AS_STRIDE;                 // [BD][BK]
    float* redv = Bs + BD * BK;                        // [BM][16]
    int*   redi = (int*)(redv + BM * 16);              // [BM][16]

    const int tid = threadIdx.x;
    const int tx  = tid & 15;        // 16 column-threads
    const int ty  = tid >> 4;        // 16 row-threads
    const int rowBase = blockIdx.x * BM;

    // ---- load A tile (64 x 256) into smem, float4 coalesced ----
    {
        const float4* in4 = (const float4*)(inputs + (size_t)rowBase * D_DIM);
        #pragma unroll
        for (int idx = tid; idx < BM * (D_DIM / 4); idx += THREADS) {
            float4 v = in4[idx];
            int r = idx >> 6;            // / (256/4)
            int d = (idx & 63) << 2;
            float* dst = As + r * AS_STRIDE + d;
            dst[0] = v.x; dst[1] = v.y; dst[2] = v.z; dst[3] = v.w;
        }
    }

    float bestv[4];
    int   bestk[4];
    #pragma unroll
    for (int i = 0; i < 4; i++) { bestv[i] = FLT_MAX; bestk[i] = 0; }

    for (int kc = 0; kc < K_CODES; kc += BK) {
        float acc[4][4];
        #pragma unroll
        for (int i = 0; i < 4; i++)
            #pragma unroll
            for (int j = 0; j < 4; j++) acc[i][j] = 0.0f;

        for (int db = 0; db < D_DIM; db += BD) {
            __syncthreads();   // previous Bs consumers done (also covers A load)
            // load B tile: Bs[d][k] = cb[(db+d)*K + kc+k], one float4/thread
            {
                int d  = tid >> 4;
                int k4 = (tid & 15) << 2;
                float4 v = *(const float4*)(cb + (size_t)(db + d) * K_CODES + kc + k4);
                float* dst = Bs + d * BK + k4;
                dst[0] = v.x; dst[1] = v.y; dst[2] = v.z; dst[3] = v.w;
            }
            __syncthreads();

            #pragma unroll
            for (int d = 0; d < BD; d++) {
                float a[4], b[4];
                #pragma unroll
                for (int i = 0; i < 4; i++)
                    a[i] = As[(ty + 16 * i) * AS_STRIDE + db + d];
                #pragma unroll
                for (int j = 0; j < 4; j++)
                    b[j] = Bs[d * BK + tx + 16 * j];
                #pragma unroll
                for (int i = 0; i < 4; i++)
                    #pragma unroll
                    for (int j = 0; j < 4; j++)
                        acc[i][j] = fmaf(a[i], b[j], acc[i][j]);
            }
        }

        // fold chunk into running argmin (dist = cnorm - 2*dot)
        #pragma unroll
        for (int j = 0; j < 4; j++) {
            int k = kc + tx + 16 * j;
            float cn = g_cnorm[k];
            #pragma unroll
            for (int i = 0; i < 4; i++) {
                float dist = fmaf(-2.0f, acc[i][j], cn);
                if (dist < bestv[i]) { bestv[i] = dist; bestk[i] = k; }
            }
        }
    }

    // ---- reduce argmin across the 16 tx-threads per row ----
    __syncthreads();
    #pragma unroll
    for (int i = 0; i < 4; i++) {
        int r = ty + 16 * i;
        redv[r * 16 + tx] = bestv[i];
        redi[r * 16 + tx] = bestk[i];
    }
    __syncthreads();

    if (tid < BM) {
        float bv = redv[tid * 16];
        int   bk = redi[tid * 16];
        #pragma unroll
        for (int t = 1; t < 16; t++) {
            float v = redv[tid * 16 + t];
            int   k = redi[tid * 16 + t];
            if (v < bv || (v == bv && k < bk)) { bv = v; bk = k; }
        }
        redi[tid * 16] = bk;
        atomicAdd(&g_counts[bk], 1);
    }
    __syncthreads();

    // ---- epilogue: write ste = x + (q - x), accumulate sum (q-x)^2 ----
    {
        int w    = tid >> 5;
        int lane = tid & 31;
        float ss = 0.0f;
        for (int r = w * 8; r < w * 8 + 8; r++) {
            int bk = redi[r * 16];
            const float* cr  = g_cT + (size_t)bk * D_DIM;
            const float* xr  = As + r * AS_STRIDE;
            float* orow = out + (size_t)(rowBase + r) * D_DIM;
            #pragma unroll
            for (int d = lane; d < D_DIM; d += 32) {
                float q = cr[d];
                float x = xr[d];
                float diff = q - x;
                orow[d] = x + diff;
                ss = fmaf(diff, diff, ss);
            }
        }
        #pragma unroll
        for (int o = 16; o; o >>= 1)
            ss += __shfl_xor_sync(0xFFFFFFFFu, ss, o);
        if (lane == 0) atomicAdd(&g_sumsq, ss);
    }
}

// ---------------------------------------------------------------------------
__global__ void k_final(float* __restrict__ out, int rows) {
    __shared__ float red[32];
    int tid = threadIdx.x;
    float p = (float)g_counts[tid] / (float)rows;
    float term = -p * logf(p + 1e-10f);
    #pragma unroll
    for (int o = 16; o; o >>= 1)
        term += __shfl_xor_sync(0xFFFFFFFFu, term, o);
    if ((tid & 31) == 0) red[tid >> 5] = term;
    __syncthreads();
    if (tid < 32) {
        float v = red[tid];
        #pragma unroll
        for (int o = 16; o; o >>= 1)
            v += __shfl_xor_sync(0xFFFFFFFFu, v, o);
        if (tid == 0) {
            float ent = v;
            float n_elems = (float)rows * (float)D_DIM;
            float mean = g_sumsq / n_elems;
            size_t base = (size_t)rows * D_DIM;
            out[base + 0] = expf(ent);          // perplexity
            out[base + 1] = mean;               // codebook_loss
            out[base + 2] = 0.25f * mean;       // commitment_loss
        }
    }
}

// ---------------------------------------------------------------------------
extern "C" void kernel_launch(void* const* d_in, const int* in_sizes, int n_in,
                              void* d_out, int out_size) {
    const float* inputs   = (const float*)d_in[0];
    const float* codebook = (const float*)d_in[1];
    float* out = (float*)d_out;

    int rows = in_sizes[0] / D_DIM;   // 32768

    cudaFuncSetAttribute(k_main, cudaFuncAttributeMaxDynamicSharedMemorySize,
                         SMEM_MAIN);

    k_init<<<1, 1024>>>();
    k_cnorm<<<K_CODES / 256, 256>>>(codebook);
    k_transpose<<<dim3(K_CODES / 32, D_DIM / 32), dim3(32, 32)>>>(codebook);
    k_main<<<rows / BM, THREADS, SMEM_MAIN>>>(inputs, codebook, out);
    k_final<<<1, 1024>>>(out, rows);
}

// round 5
// speedup vs baseline: 2.5045x; 2.5045x over previous
#include <cuda_runtime.h>
#include <cuda_bf16.h>
#include <math.h>
#include <float.h>
#include <stdint.h>

// ============================================================================
// VectorQuantizer via warp-level bf16-split mma.sync + exact fp32 rescore.
// dist(n,k) = |x|^2 - 2 x.c + |c|^2 ; argmin over (cnorm[k] - 2*dot).
// Split GEMM (xh.ch + xh.cl + xl.ch) ranks candidates; rows whose top-2
// margin < EPS are re-decided with an exact fp32 dot (matches reference
// accuracy class). out = [ste, perplexity, codebook_loss, commitment_loss]
// ============================================================================

#define D_DIM   256
#define K_CODES 1024
#define BM      128
#define BN      128
#define NCHUNK  (K_CODES / BN)
#define KS      64
#define NSLICES (NCHUNK * (D_DIM / KS))  // 32
#define THREADS 256
#define EPS_MARGIN 1e-2f

#define AST 264
#define BST 72

#define OFS_AH    0
#define ABYTES    (BM * AST * 2)
#define OFS_AL    (OFS_AH + ABYTES)
#define OFS_B     (OFS_AL + ABYTES)
#define BBYTES    (BN * BST * 2)
#define OFS_CN    (OFS_B + 4 * BBYTES)
#define OFS_REDV  (OFS_CN + K_CODES * 4)
#define OFS_REDI  (OFS_REDV + BM * 4 * 4)
#define OFS_REDV2 (OFS_REDI + BM * 4 * 4)
#define OFS_REDI2 (OFS_REDV2 + BM * 4 * 4)
#define OFS_BK    (OFS_REDI2 + BM * 4 * 4)
#define SMEM_MAIN (OFS_BK + BM * 4)

__device__ float          g_cT[K_CODES * D_DIM];
__device__ __nv_bfloat16  g_cbh[K_CODES * D_DIM];
__device__ __nv_bfloat16  g_cbl[K_CODES * D_DIM];
__device__ float          g_cnorm[K_CODES];
__device__ int            g_counts[K_CODES];
__device__ float          g_sumsq;

// ---------------------------------------------------------------------------
__device__ __forceinline__ uint32_t smem_u32(const void* p) {
    uint32_t a;
    asm("{ .reg .u64 t; cvta.to.shared.u64 t, %1; cvt.u32.u64 %0, t; }"
        : "=r"(a) : "l"(p));
    return a;
}

#define CP16(sa, ga) \
    asm volatile("cp.async.cg.shared.global [%0], [%1], 16;" \
                 :: "r"(sa), "l"(ga) : "memory")
#define CP_COMMIT() asm volatile("cp.async.commit_group;" ::: "memory")
#define CP_WAIT1()  asm volatile("cp.async.wait_group 1;" ::: "memory")

__device__ __forceinline__ void ldmx4(uint32_t& r0, uint32_t& r1,
                                      uint32_t& r2, uint32_t& r3, uint32_t a) {
    asm volatile("ldmatrix.sync.aligned.m8n8.x4.shared.b16 {%0,%1,%2,%3}, [%4];"
                 : "=r"(r0), "=r"(r1), "=r"(r2), "=r"(r3) : "r"(a));
}

#define MMA_BF16(c, a, b)                                                     \
    asm volatile("mma.sync.aligned.m16n8k16.row.col.f32.bf16.bf16.f32 "       \
                 "{%0,%1,%2,%3}, {%4,%5,%6,%7}, {%8,%9}, {%0,%1,%2,%3};"      \
                 : "+f"((c)[0]), "+f"((c)[1]), "+f"((c)[2]), "+f"((c)[3])     \
                 : "r"((a)[0]), "r"((a)[1]), "r"((a)[2]), "r"((a)[3]),        \
                   "r"((b)[0]), "r"((b)[1]))

// ============================================================================
__global__ void k_init() {
    int t = threadIdx.x;
    if (t < K_CODES) g_counts[t] = 0;
    if (t == 0) g_sumsq = 0.0f;
}

__global__ void k_cnorm(const float* __restrict__ cb) {
    int k = blockIdx.x * blockDim.x + threadIdx.x;
    float s = 0.0f;
    #pragma unroll 8
    for (int d = 0; d < D_DIM; d++) {
        float v = cb[d * K_CODES + k];
        s += v * v;
    }
    g_cnorm[k] = s;
}

__global__ void k_prep(const float* __restrict__ cb) {
    __shared__ float t[32][33];
    int k = blockIdx.x * 32 + threadIdx.x;
    int d = blockIdx.y * 32 + threadIdx.y;
    t[threadIdx.y][threadIdx.x] = cb[d * K_CODES + k];
    __syncthreads();
    int ko = blockIdx.x * 32 + threadIdx.y;
    int dd = blockIdx.y * 32 + threadIdx.x;
    float v = t[threadIdx.x][threadIdx.y];
    size_t o = (size_t)ko * D_DIM + dd;
    g_cT[o] = v;
    __nv_bfloat16 h = __float2bfloat16(v);
    g_cbh[o] = h;
    g_cbl[o] = __float2bfloat16(v - __bfloat162float(h));
}

// ============================================================================
__global__ __launch_bounds__(THREADS, 1)
void k_main(const float* __restrict__ inputs, float* __restrict__ out) {
    extern __shared__ char smem[];
    const uint32_t sb = smem_u32(smem);
    const int tid    = threadIdx.x;
    const int wid    = tid >> 5;
    const int lane   = tid & 31;
    const int warp_m = wid & 1;
    const int warp_n = wid >> 1;
    const int g      = lane >> 2;
    const int t2     = lane & 3;
    const int rowBase = blockIdx.x * BM;

    float* s_cnorm = (float*)(smem + OFS_CN);
    float* s_redv  = (float*)(smem + OFS_REDV);
    int*   s_redi  = (int*)(smem + OFS_REDI);
    float* s_redv2 = (float*)(smem + OFS_REDV2);
    int*   s_redi2 = (int*)(smem + OFS_REDI2);
    int*   s_bk    = (int*)(smem + OFS_BK);

    // ---- A conversion: 128x256 fp32 -> bf16 hi/lo in smem ----
    {
        const float4* in4 = (const float4*)(inputs + (size_t)rowBase * D_DIM);
        #pragma unroll
        for (int i = 0; i < 32; i++) {
            int idx = tid + i * THREADS;
            int r = idx >> 6;
            int d = (idx & 63) << 2;
            float4 v = in4[idx];
            __nv_bfloat16 h0 = __float2bfloat16(v.x);
            __nv_bfloat16 h1 = __float2bfloat16(v.y);
            __nv_bfloat16 h2 = __float2bfloat16(v.z);
            __nv_bfloat16 h3 = __float2bfloat16(v.w);
            __nv_bfloat16 l0 = __float2bfloat16(v.x - __bfloat162float(h0));
            __nv_bfloat16 l1 = __float2bfloat16(v.y - __bfloat162float(h1));
            __nv_bfloat16 l2 = __float2bfloat16(v.z - __bfloat162float(h2));
            __nv_bfloat16 l3 = __float2bfloat16(v.w - __bfloat162float(h3));
            uint64_t ph = (uint64_t)__bfloat16_as_ushort(h0)
                        | ((uint64_t)__bfloat16_as_ushort(h1) << 16)
                        | ((uint64_t)__bfloat16_as_ushort(h2) << 32)
                        | ((uint64_t)__bfloat16_as_ushort(h3) << 48);
            uint64_t pl = (uint64_t)__bfloat16_as_ushort(l0)
                        | ((uint64_t)__bfloat16_as_ushort(l1) << 16)
                        | ((uint64_t)__bfloat16_as_ushort(l2) << 32)
                        | ((uint64_t)__bfloat16_as_ushort(l3) << 48);
            uint32_t boff = (uint32_t)(r * AST + d) * 2;
            *(uint64_t*)(smem + OFS_AH + boff) = ph;
            *(uint64_t*)(smem + OFS_AL + boff) = pl;
        }
        #pragma unroll
        for (int i = 0; i < K_CODES / THREADS; i++)
            s_cnorm[tid + i * THREADS] = g_cnorm[tid + i * THREADS];
    }

    auto fill = [&](int s, int buf) {
        int chunk = s >> 2, ds = s & 3;
        const char* srcH = (const char*)(g_cbh + (size_t)(chunk * BN) * D_DIM + ds * KS);
        const char* srcL = (const char*)(g_cbl + (size_t)(chunk * BN) * D_DIM + ds * KS);
        uint32_t dstH = sb + OFS_B + buf * 2 * BBYTES;
        uint32_t dstL = dstH + BBYTES;
        #pragma unroll
        for (int i = 0; i < 4; i++) {
            int t = tid + i * THREADS;
            int code = t >> 3, seg = t & 7;
            uint32_t so = (uint32_t)(code * BST * 2 + seg * 16);
            size_t   go = (size_t)code * (D_DIM * 2) + seg * 16;
            CP16(dstH + so, srcH + go);
            CP16(dstL + so, srcL + go);
        }
    };
    fill(0, 0);
    CP_COMMIT();

    const int laneRowA = (lane & 7) + ((lane >> 3) & 1) * 8;
    const int laneColA = ((lane >> 4) & 1) * 8;
    const int laneRowB = (lane & 7) + ((lane >> 4) & 1) * 8;
    const int laneColB = ((lane >> 3) & 1) * 8;

    float acc[4][4][4];
    #pragma unroll
    for (int mt = 0; mt < 4; mt++)
        #pragma unroll
        for (int nt = 0; nt < 4; nt++)
            #pragma unroll
            for (int e = 0; e < 4; e++) acc[mt][nt][e] = 0.0f;

    // top-2 per row-slot b (8 slots)
    float v1[8], v2[8];
    int   k1[8], k2[8];
    #pragma unroll
    for (int b = 0; b < 8; b++) {
        v1[b] = FLT_MAX; v2[b] = FLT_MAX; k1[b] = 0x7FFFFFFF; k2[b] = 0x7FFFFFFF;
    }

    for (int s = 0; s < NSLICES; s++) {
        if (s < NSLICES - 1) fill(s + 1, (s + 1) & 1);
        CP_COMMIT();
        CP_WAIT1();
        __syncthreads();

        const int ds  = s & 3;
        const int buf = s & 1;
        const uint32_t bH = sb + OFS_B + buf * 2 * BBYTES;

        #pragma unroll
        for (int kstep = 0; kstep < 4; kstep++) {
            const int ka = ds * KS + kstep * 16;
            const int kb = kstep * 16;

            uint32_t ah[4][4], al[4][4], bh[4][2], bl[4][2];
            #pragma unroll
            for (int p = 0; p < 2; p++) {
                uint32_t addr = bH + (uint32_t)((warp_n * 32 + p * 16 + laneRowB) * BST
                                                + kb + laneColB) * 2;
                ldmx4(bh[p*2][0], bh[p*2][1], bh[p*2+1][0], bh[p*2+1][1], addr);
                addr += BBYTES;
                ldmx4(bl[p*2][0], bl[p*2][1], bl[p*2+1][0], bl[p*2+1][1], addr);
            }
            #pragma unroll
            for (int mt = 0; mt < 4; mt++) {
                uint32_t ro = (uint32_t)((warp_m * 64 + mt * 16 + laneRowA) * AST
                                         + ka + laneColA) * 2;
                ldmx4(ah[mt][0], ah[mt][1], ah[mt][2], ah[mt][3], sb + OFS_AH + ro);
                ldmx4(al[mt][0], al[mt][1], al[mt][2], al[mt][3], sb + OFS_AL + ro);
            }
            #pragma unroll
            for (int mt = 0; mt < 4; mt++)
                #pragma unroll
                for (int nt = 0; nt < 4; nt++) {
                    MMA_BF16(acc[mt][nt], ah[mt], bh[nt]);
                    MMA_BF16(acc[mt][nt], ah[mt], bl[nt]);
                    MMA_BF16(acc[mt][nt], al[mt], bh[nt]);
                }
        }

        if ((s & 3) == 3) {
            const int chunk = s >> 2;
            #pragma unroll
            for (int mt = 0; mt < 4; mt++)
                #pragma unroll
                for (int nt = 0; nt < 4; nt++)
                    #pragma unroll
                    for (int e = 0; e < 4; e++) {
                        int k = chunk * BN + warp_n * 32 + nt * 8 + t2 * 2 + (e & 1);
                        float dist = fmaf(-2.0f, acc[mt][nt][e], s_cnorm[k]);
                        int b = mt * 2 + (e >> 1);
                        if (dist < v1[b] || (dist == v1[b] && k < k1[b])) {
                            v2[b] = v1[b]; k2[b] = k1[b];
                            v1[b] = dist;  k1[b] = k;
                        } else if (dist < v2[b]) {
                            v2[b] = dist; k2[b] = k;
                        }
                        acc[mt][nt][e] = 0.0f;
                    }
        }
        __syncthreads();
    }

    // ---- top-2 merge across t2 lanes ----
    #pragma unroll
    for (int b = 0; b < 8; b++) {
        #pragma unroll
        for (int off = 1; off <= 2; off <<= 1) {
            float ov1 = __shfl_xor_sync(0xFFFFFFFFu, v1[b], off);
            int   ok1 = __shfl_xor_sync(0xFFFFFFFFu, k1[b], off);
            float ov2 = __shfl_xor_sync(0xFFFFFFFFu, v2[b], off);
            int   ok2 = __shfl_xor_sync(0xFFFFFFFFu, k2[b], off);
            float w1, lv; int j1, lk;
            if (ov1 < v1[b] || (ov1 == v1[b] && ok1 < k1[b])) {
                w1 = ov1; j1 = ok1; lv = v1[b]; lk = k1[b];
            } else {
                w1 = v1[b]; j1 = k1[b]; lv = ov1; lk = ok1;
            }
            float w2 = lv; int j2 = lk;
            if (v2[b] < w2) { w2 = v2[b]; j2 = k2[b]; }
            if (ov2  < w2) { w2 = ov2;  j2 = ok2;  }
            v1[b] = w1; k1[b] = j1; v2[b] = w2; k2[b] = j2;
        }
    }
    if (t2 == 0) {
        #pragma unroll
        for (int b = 0; b < 8; b++) {
            int mt = b >> 1, hi = b & 1;
            int row = warp_m * 64 + mt * 16 + g + hi * 8;
            s_redv[row * 4 + warp_n]  = v1[b];
            s_redi[row * 4 + warp_n]  = k1[b];
            s_redv2[row * 4 + warp_n] = v2[b];
            s_redi2[row * 4 + warp_n] = k2[b];
        }
    }
    __syncthreads();

    // ---- per-row final merge + exact rescore if margin small ----
    if (tid < BM) {
        float bv1 = s_redv[tid * 4], bv2 = s_redv2[tid * 4];
        int   bk1 = s_redi[tid * 4], bk2 = s_redi2[tid * 4];
        #pragma unroll
        for (int w = 1; w < 4; w++) {
            float ov1 = s_redv[tid * 4 + w],  ov2 = s_redv2[tid * 4 + w];
            int   ok1 = s_redi[tid * 4 + w],  ok2 = s_redi2[tid * 4 + w];
            float w1, lv; int j1, lk;
            if (ov1 < bv1 || (ov1 == bv1 && ok1 < bk1)) {
                w1 = ov1; j1 = ok1; lv = bv1; lk = bk1;
            } else {
                w1 = bv1; j1 = bk1; lv = ov1; lk = ok1;
            }
            float w2 = lv; int j2 = lk;
            if (bv2 < w2) { w2 = bv2; j2 = bk2; }
            if (ov2 < w2) { w2 = ov2; j2 = ok2; }
            bv1 = w1; bk1 = j1; bv2 = w2; bk2 = j2;
        }
        int bk = bk1;
        if (bv2 - bv1 < EPS_MARGIN) {
            const float* xr = inputs + (size_t)(rowBase + tid) * D_DIM;
            const float* c1 = g_cT + (size_t)bk1 * D_DIM;
            const float* c2 = g_cT + (size_t)bk2 * D_DIM;
            float d1 = 0.0f, d2 = 0.0f;
            for (int d = 0; d < D_DIM; d++) {
                float x = __ldg(xr + d);
                d1 = fmaf(x, __ldg(c1 + d), d1);
                d2 = fmaf(x, __ldg(c2 + d), d2);
            }
            float e1 = fmaf(-2.0f, d1, s_cnorm[bk1]);
            float e2 = fmaf(-2.0f, d2, s_cnorm[bk2]);
            if (e2 < e1 || (e2 == e1 && bk2 < bk1)) bk = bk2;
        }
        s_bk[tid] = bk;
        atomicAdd(&g_counts[bk], 1);
    }
    __syncthreads();

    // ---- epilogue: ste + sum (q-x)^2, exact fp32 x from gmem ----
    {
        float ss = 0.0f;
        #pragma unroll
        for (int rr = 0; rr < 16; rr++) {
            const int r = wid * 16 + rr;
            const int bk = s_bk[r];
            const float4* x4 = (const float4*)(inputs + (size_t)(rowBase + r) * D_DIM);
            const float4* q4 = (const float4*)(g_cT + (size_t)bk * D_DIM);
            float4* o4 = (float4*)(out + (size_t)(rowBase + r) * D_DIM);
            #pragma unroll
            for (int h = 0; h < 2; h++) {
                int d4 = lane + h * 32;
                float4 x = x4[d4];
                float4 q = q4[d4];
                float d0 = q.x - x.x, d1 = q.y - x.y, d2 = q.z - x.z, d3 = q.w - x.w;
                float4 o;
                o.x = x.x + d0; o.y = x.y + d1; o.z = x.z + d2; o.w = x.w + d3;
                o4[d4] = o;
                ss = fmaf(d0, d0, ss); ss = fmaf(d1, d1, ss);
                ss = fmaf(d2, d2, ss); ss = fmaf(d3, d3, ss);
            }
        }
        #pragma unroll
        for (int o = 16; o; o >>= 1)
            ss += __shfl_xor_sync(0xFFFFFFFFu, ss, o);
        if (lane == 0) atomicAdd(&g_sumsq, ss);
    }
}

// ============================================================================
__global__ void k_final(float* __restrict__ out, int rows) {
    __shared__ float red[32];
    int tid = threadIdx.x;
    float p = (float)g_counts[tid] / (float)rows;
    float term = -p * logf(p + 1e-10f);
    #pragma unroll
    for (int o = 16; o; o >>= 1)
        term += __shfl_xor_sync(0xFFFFFFFFu, term, o);
    if ((tid & 31) == 0) red[tid >> 5] = term;
    __syncthreads();
    if (tid < 32) {
        float v = red[tid];
        #pragma unroll
        for (int o = 16; o; o >>= 1)
            v += __shfl_xor_sync(0xFFFFFFFFu, v, o);
        if (tid == 0) {
            float mean = g_sumsq / ((float)rows * (float)D_DIM);
            size_t base = (size_t)rows * D_DIM;
            out[base + 0] = expf(v);
            out[base + 1] = mean;
            out[base + 2] = 0.25f * mean;
        }
    }
}

// ============================================================================
extern "C" void kernel_launch(void* const* d_in, const int* in_sizes, int n_in,
                              void* d_out, int out_size) {
    const float* inputs   = (const float*)d_in[0];
    const float* codebook = (const float*)d_in[1];
    float* out = (float*)d_out;
    int rows = in_sizes[0] / D_DIM;

    cudaFuncSetAttribute(k_main, cudaFuncAttributeMaxDynamicSharedMemorySize, SMEM_MAIN);

    k_init<<<1, 1024>>>();
    k_cnorm<<<K_CODES / 256, 256>>>(codebook);
    k_prep<<<dim3(K_CODES / 32, D_DIM / 32), dim3(32, 32)>>>(codebook);
    k_main<<<rows / BM, THREADS, SMEM_MAIN>>>(inputs, out);
    k_final<<<1, 1024>>>(out, rows);
}

// round 7
// speedup vs baseline: 2.6429x; 1.0552x over previous
#include <cuda_runtime.h>
#include <cuda_bf16.h>
#include <math.h>
#include <float.h>
#include <stdint.h>

// ============================================================================
// VectorQuantizer via warp-level bf16-split mma.sync + exact fp32 rescore.
// 512 threads / 16 warps (4x4 warp grid), warp tile 32x32.
// dist(n,k) = |x|^2 - 2 x.c + |c|^2 ; argmin over (cnorm[k] - 2*dot).
// Split GEMM (xh.ch + xh.cl + xl.ch) ranks candidates; rows whose top-2
// margin < EPS are re-decided with an exact fp32 dot.
// out = [ste, perplexity, codebook_loss, commitment_loss]
// ============================================================================

#define D_DIM   256
#define K_CODES 1024
#define BM      128
#define BN      128
#define NCHUNK  (K_CODES / BN)
#define KS      64
#define NSLICES (NCHUNK * (D_DIM / KS))  // 32
#define THREADS 512
#define EPS_MARGIN 1e-2f

#define AST 264
#define BST 72

#define OFS_AH    0
#define ABYTES    (BM * AST * 2)
#define OFS_AL    (OFS_AH + ABYTES)
#define OFS_B     (OFS_AL + ABYTES)
#define BBYTES    (BN * BST * 2)
#define OFS_CN    (OFS_B + 4 * BBYTES)
#define OFS_REDV  (OFS_CN + K_CODES * 4)
#define OFS_REDI  (OFS_REDV + BM * 4 * 4)
#define OFS_REDV2 (OFS_REDI + BM * 4 * 4)
#define OFS_REDI2 (OFS_REDV2 + BM * 4 * 4)
#define OFS_BK    (OFS_REDI2 + BM * 4 * 4)
#define SMEM_MAIN (OFS_BK + BM * 4)

__device__ float          g_cT[K_CODES * D_DIM];
__device__ __nv_bfloat16  g_cbh[K_CODES * D_DIM];
__device__ __nv_bfloat16  g_cbl[K_CODES * D_DIM];
__device__ float          g_cnorm[K_CODES];
__device__ int            g_counts[K_CODES];
__device__ float          g_sumsq;

// ---------------------------------------------------------------------------
__device__ __forceinline__ uint32_t smem_u32(const void* p) {
    uint32_t a;
    asm("{ .reg .u64 t; cvta.to.shared.u64 t, %1; cvt.u32.u64 %0, t; }"
        : "=r"(a) : "l"(p));
    return a;
}

#define CP16(sa, ga) \
    asm volatile("cp.async.cg.shared.global [%0], [%1], 16;" \
                 :: "r"(sa), "l"(ga) : "memory")
#define CP_COMMIT() asm volatile("cp.async.commit_group;" ::: "memory")
#define CP_WAIT1()  asm volatile("cp.async.wait_group 1;" ::: "memory")

__device__ __forceinline__ void ldmx4(uint32_t& r0, uint32_t& r1,
                                      uint32_t& r2, uint32_t& r3, uint32_t a) {
    asm volatile("ldmatrix.sync.aligned.m8n8.x4.shared.b16 {%0,%1,%2,%3}, [%4];"
                 : "=r"(r0), "=r"(r1), "=r"(r2), "=r"(r3) : "r"(a));
}

#define MMA_BF16(c, a, b)                                                     \
    asm volatile("mma.sync.aligned.m16n8k16.row.col.f32.bf16.bf16.f32 "       \
                 "{%0,%1,%2,%3}, {%4,%5,%6,%7}, {%8,%9}, {%0,%1,%2,%3};"      \
                 : "+f"((c)[0]), "+f"((c)[1]), "+f"((c)[2]), "+f"((c)[3])     \
                 : "r"((a)[0]), "r"((a)[1]), "r"((a)[2]), "r"((a)[3]),        \
                   "r"((b)[0]), "r"((b)[1]))

// ============================================================================
__global__ void k_init() {
    int t = threadIdx.x;
    if (t < K_CODES) g_counts[t] = 0;
    if (t == 0) g_sumsq = 0.0f;
}

__global__ void k_cnorm(const float* __restrict__ cb) {
    int k = blockIdx.x * blockDim.x + threadIdx.x;
    float s = 0.0f;
    #pragma unroll 8
    for (int d = 0; d < D_DIM; d++) {
        float v = cb[d * K_CODES + k];
        s += v * v;
    }
    g_cnorm[k] = s;
}

__global__ void k_prep(const float* __restrict__ cb) {
    __shared__ float t[32][33];
    int k = blockIdx.x * 32 + threadIdx.x;
    int d = blockIdx.y * 32 + threadIdx.y;
    t[threadIdx.y][threadIdx.x] = cb[d * K_CODES + k];
    __syncthreads();
    int ko = blockIdx.x * 32 + threadIdx.y;
    int dd = blockIdx.y * 32 + threadIdx.x;
    float v = t[threadIdx.x][threadIdx.y];
    size_t o = (size_t)ko * D_DIM + dd;
    g_cT[o] = v;
    __nv_bfloat16 h = __float2bfloat16(v);
    g_cbh[o] = h;
    g_cbl[o] = __float2bfloat16(v - __bfloat162float(h));
}

// ============================================================================
// 512 threads: warp grid 4 (m) x 4 (n); warp tile 32 rows x 32 codes.
// ============================================================================
__global__ __launch_bounds__(THREADS, 1)
void k_main(const float* __restrict__ inputs, float* __restrict__ out) {
    extern __shared__ char smem[];
    const uint32_t sb = smem_u32(smem);
    const int tid    = threadIdx.x;
    const int wid    = tid >> 5;
    const int lane   = tid & 31;
    const int warp_m = wid & 3;          // 0..3 (32-row groups)
    const int warp_n = wid >> 2;         // 0..3 (32-code groups)
    const int g      = lane >> 2;
    const int t2     = lane & 3;
    const int rowBase = blockIdx.x * BM;

    float* s_cnorm = (float*)(smem + OFS_CN);
    float* s_redv  = (float*)(smem + OFS_REDV);
    int*   s_redi  = (int*)(smem + OFS_REDI);
    float* s_redv2 = (float*)(smem + OFS_REDV2);
    int*   s_redi2 = (int*)(smem + OFS_REDI2);
    int*   s_bk    = (int*)(smem + OFS_BK);

    // ---- A conversion: 128x256 fp32 -> bf16 hi/lo in smem ----
    {
        const float4* in4 = (const float4*)(inputs + (size_t)rowBase * D_DIM);
        #pragma unroll
        for (int i = 0; i < 16; i++) {
            int idx = tid + i * THREADS;      // 0..8191
            int r = idx >> 6;
            int d = (idx & 63) << 2;
            float4 v = in4[idx];
            __nv_bfloat16 h0 = __float2bfloat16(v.x);
            __nv_bfloat16 h1 = __float2bfloat16(v.y);
            __nv_bfloat16 h2 = __float2bfloat16(v.z);
            __nv_bfloat16 h3 = __float2bfloat16(v.w);
            __nv_bfloat16 l0 = __float2bfloat16(v.x - __bfloat162float(h0));
            __nv_bfloat16 l1 = __float2bfloat16(v.y - __bfloat162float(h1));
            __nv_bfloat16 l2 = __float2bfloat16(v.z - __bfloat162float(h2));
            __nv_bfloat16 l3 = __float2bfloat16(v.w - __bfloat162float(h3));
            uint64_t ph = (uint64_t)__bfloat16_as_ushort(h0)
                        | ((uint64_t)__bfloat16_as_ushort(h1) << 16)
                        | ((uint64_t)__bfloat16_as_ushort(h2) << 32)
                        | ((uint64_t)__bfloat16_as_ushort(h3) << 48);
            uint64_t pl = (uint64_t)__bfloat16_as_ushort(l0)
                        | ((uint64_t)__bfloat16_as_ushort(l1) << 16)
                        | ((uint64_t)__bfloat16_as_ushort(l2) << 32)
                        | ((uint64_t)__bfloat16_as_ushort(l3) << 48);
            uint32_t boff = (uint32_t)(r * AST + d) * 2;
            *(uint64_t*)(smem + OFS_AH + boff) = ph;
            *(uint64_t*)(smem + OFS_AL + boff) = pl;
        }
        #pragma unroll
        for (int i = 0; i < K_CODES / THREADS; i++)
            s_cnorm[tid + i * THREADS] = g_cnorm[tid + i * THREADS];
    }

    auto fill = [&](int s, int buf) {
        int chunk = s >> 2, ds = s & 3;
        const char* srcH = (const char*)(g_cbh + (size_t)(chunk * BN) * D_DIM + ds * KS);
        const char* srcL = (const char*)(g_cbl + (size_t)(chunk * BN) * D_DIM + ds * KS);
        uint32_t dstH = sb + OFS_B + buf * 2 * BBYTES;
        uint32_t dstL = dstH + BBYTES;
        #pragma unroll
        for (int i = 0; i < 2; i++) {
            int t = tid + i * THREADS;        // 0..1023
            int code = t >> 3, seg = t & 7;
            uint32_t so = (uint32_t)(code * BST * 2 + seg * 16);
            size_t   go = (size_t)code * (D_DIM * 2) + seg * 16;
            CP16(dstH + so, srcH + go);
            CP16(dstL + so, srcL + go);
        }
    };
    fill(0, 0);
    CP_COMMIT();

    const int laneRowA = (lane & 7) + ((lane >> 3) & 1) * 8;
    const int laneColA = ((lane >> 4) & 1) * 8;
    const int laneRowB = (lane & 7) + ((lane >> 4) & 1) * 8;
    const int laneColB = ((lane >> 3) & 1) * 8;

    float acc[2][4][4];
    #pragma unroll
    for (int mt = 0; mt < 2; mt++)
        #pragma unroll
        for (int nt = 0; nt < 4; nt++)
            #pragma unroll
            for (int e = 0; e < 4; e++) acc[mt][nt][e] = 0.0f;

    // top-2 per row-slot b (4 slots: mt*2 + e_hi)
    float v1[4], v2[4];
    int   k1[4], k2[4];
    #pragma unroll
    for (int b = 0; b < 4; b++) {
        v1[b] = FLT_MAX; v2[b] = FLT_MAX; k1[b] = 0x7FFFFFFF; k2[b] = 0x7FFFFFFF;
    }

    for (int s = 0; s < NSLICES; s++) {
        if (s < NSLICES - 1) fill(s + 1, (s + 1) & 1);
        CP_COMMIT();
        CP_WAIT1();
        __syncthreads();

        const int ds  = s & 3;
        const int buf = s & 1;
        const uint32_t bH = sb + OFS_B + buf * 2 * BBYTES;

        #pragma unroll
        for (int kstep = 0; kstep < 4; kstep++) {
            const int ka = ds * KS + kstep * 16;
            const int kb = kstep * 16;

            uint32_t ah[2][4], al[2][4], bh[4][2], bl[4][2];
            #pragma unroll
            for (int p = 0; p < 2; p++) {
                uint32_t addr = bH + (uint32_t)((warp_n * 32 + p * 16 + laneRowB) * BST
                                                + kb + laneColB) * 2;
                ldmx4(bh[p*2][0], bh[p*2][1], bh[p*2+1][0], bh[p*2+1][1], addr);
                addr += BBYTES;
                ldmx4(bl[p*2][0], bl[p*2][1], bl[p*2+1][0], bl[p*2+1][1], addr);
            }
            #pragma unroll
            for (int mt = 0; mt < 2; mt++) {
                uint32_t ro = (uint32_t)((warp_m * 32 + mt * 16 + laneRowA) * AST
                                         + ka + laneColA) * 2;
                ldmx4(ah[mt][0], ah[mt][1], ah[mt][2], ah[mt][3], sb + OFS_AH + ro);
                ldmx4(al[mt][0], al[mt][1], al[mt][2], al[mt][3], sb + OFS_AL + ro);
            }
            #pragma unroll
            for (int mt = 0; mt < 2; mt++)
                #pragma unroll
                for (int nt = 0; nt < 4; nt++) {
                    MMA_BF16(acc[mt][nt], ah[mt], bh[nt]);
                    MMA_BF16(acc[mt][nt], ah[mt], bl[nt]);
                    MMA_BF16(acc[mt][nt], al[mt], bh[nt]);
                }
        }

        if ((s & 3) == 3) {
            const int chunk = s >> 2;
            #pragma unroll
            for (int mt = 0; mt < 2; mt++)
                #pragma unroll
                for (int nt = 0; nt < 4; nt++)
                    #pragma unroll
                    for (int e = 0; e < 4; e++) {
                        int k = chunk * BN + warp_n * 32 + nt * 8 + t2 * 2 + (e & 1);
                        float dist = fmaf(-2.0f, acc[mt][nt][e], s_cnorm[k]);
                        int b = mt * 2 + (e >> 1);
                        if (dist < v1[b] || (dist == v1[b] && k < k1[b])) {
                            v2[b] = v1[b]; k2[b] = k1[b];
                            v1[b] = dist;  k1[b] = k;
                        } else if (dist < v2[b]) {
                            v2[b] = dist; k2[b] = k;
                        }
                        acc[mt][nt][e] = 0.0f;
                    }
        }
        __syncthreads();
    }

    // ---- top-2 merge across t2 lanes ----
    #pragma unroll
    for (int b = 0; b < 4; b++) {
        #pragma unroll
        for (int off = 1; off <= 2; off <<= 1) {
            float ov1 = __shfl_xor_sync(0xFFFFFFFFu, v1[b], off);
            int   ok1 = __shfl_xor_sync(0xFFFFFFFFu, k1[b], off);
            float ov2 = __shfl_xor_sync(0xFFFFFFFFu, v2[b], off);
            int   ok2 = __shfl_xor_sync(0xFFFFFFFFu, k2[b], off);
            float w1, lv; int j1, lk;
            if (ov1 < v1[b] || (ov1 == v1[b] && ok1 < k1[b])) {
                w1 = ov1; j1 = ok1; lv = v1[b]; lk = k1[b];
            } else {
                w1 = v1[b]; j1 = k1[b]; lv = ov1; lk = ok1;
            }
            float w2 = lv; int j2 = lk;
            if (v2[b] < w2) { w2 = v2[b]; j2 = k2[b]; }
            if (ov2  < w2) { w2 = ov2;  j2 = ok2;  }
            v1[b] = w1; k1[b] = j1; v2[b] = w2; k2[b] = j2;
        }
    }
    if (t2 == 0) {
        #pragma unroll
        for (int b = 0; b < 4; b++) {
            int mt = b >> 1, hi = b & 1;
            int row = warp_m * 32 + mt * 16 + g + hi * 8;
            s_redv[row * 4 + warp_n]  = v1[b];
            s_redi[row * 4 + warp_n]  = k1[b];
            s_redv2[row * 4 + warp_n] = v2[b];
            s_redi2[row * 4 + warp_n] = k2[b];
        }
    }
    __syncthreads();

    // ---- per-row final merge + exact rescore if margin small ----
    if (tid < BM) {
        float bv1 = s_redv[tid * 4], bv2 = s_redv2[tid * 4];
        int   bk1 = s_redi[tid * 4], bk2 = s_redi2[tid * 4];
        #pragma unroll
        for (int w = 1; w < 4; w++) {
            float ov1 = s_redv[tid * 4 + w],  ov2 = s_redv2[tid * 4 + w];
            int   ok1 = s_redi[tid * 4 + w],  ok2 = s_redi2[tid * 4 + w];
            float w1, lv; int j1, lk;
            if (ov1 < bv1 || (ov1 == bv1 && ok1 < bk1)) {
                w1 = ov1; j1 = ok1; lv = bv1; lk = bk1;
            } else {
                w1 = bv1; j1 = bk1; lv = ov1; lk = ok1;
            }
            float w2 = lv; int j2 = lk;
            if (bv2 < w2) { w2 = bv2; j2 = bk2; }
            if (ov2 < w2) { w2 = ov2; j2 = ok2; }
            bv1 = w1; bk1 = j1; bv2 = w2; bk2 = j2;
        }
        int bk = bk1;
        if (bv2 - bv1 < EPS_MARGIN) {
            const float* xr = inputs + (size_t)(rowBase + tid) * D_DIM;
            const float* c1 = g_cT + (size_t)bk1 * D_DIM;
            const float* c2 = g_cT + (size_t)bk2 * D_DIM;
            float d1 = 0.0f, d2 = 0.0f;
            for (int d = 0; d < D_DIM; d++) {
                float x = __ldg(xr + d);
                d1 = fmaf(x, __ldg(c1 + d), d1);
                d2 = fmaf(x, __ldg(c2 + d), d2);
            }
            float e1 = fmaf(-2.0f, d1, s_cnorm[bk1]);
            float e2 = fmaf(-2.0f, d2, s_cnorm[bk2]);
            if (e2 < e1 || (e2 == e1 && bk2 < bk1)) bk = bk2;
        }
        s_bk[tid] = bk;
        atomicAdd(&g_counts[bk], 1);
    }
    __syncthreads();

    // ---- epilogue: ste + sum (q-x)^2, exact fp32 x from gmem ----
    {
        float ss = 0.0f;
        #pragma unroll
        for (int rr = 0; rr < 8; rr++) {
            const int r = wid * 8 + rr;
            const int bk = s_bk[r];
            const float4* x4 = (const float4*)(inputs + (size_t)(rowBase + r) * D_DIM);
            const float4* q4 = (const float4*)(g_cT + (size_t)bk * D_DIM);
            float4* o4 = (float4*)(out + (size_t)(rowBase + r) * D_DIM);
            #pragma unroll
            for (int h = 0; h < 2; h++) {
                int d4 = lane + h * 32;
                float4 x = x4[d4];
                float4 q = q4[d4];
                float d0 = q.x - x.x, d1 = q.y - x.y, d2 = q.z - x.z, d3 = q.w - x.w;
                float4 o;
                o.x = x.x + d0; o.y = x.y + d1; o.z = x.z + d2; o.w = x.w + d3;
                o4[d4] = o;
                ss = fmaf(d0, d0, ss); ss = fmaf(d1, d1, ss);
                ss = fmaf(d2, d2, ss); ss = fmaf(d3, d3, ss);
            }
        }
        #pragma unroll
        for (int o = 16; o; o >>= 1)
            ss += __shfl_xor_sync(0xFFFFFFFFu, ss, o);
        if (lane == 0) atomicAdd(&g_sumsq, ss);
    }
}

// ============================================================================
__global__ void k_final(float* __restrict__ out, int rows) {
    __shared__ float red[32];
    int tid = threadIdx.x;
    float p = (float)g_counts[tid] / (float)rows;
    float term = -p * logf(p + 1e-10f);
    #pragma unroll
    for (int o = 16; o; o >>= 1)
        term += __shfl_xor_sync(0xFFFFFFFFu, term, o);
    if ((tid & 31) == 0) red[tid >> 5] = term;
    __syncthreads();
    if (tid < 32) {
        float v = red[tid];
        #pragma unroll
        for (int o = 16; o; o >>= 1)
            v += __shfl_xor_sync(0xFFFFFFFFu, v, o);
        if (tid == 0) {
            float mean = g_sumsq / ((float)rows * (float)D_DIM);
            size_t base = (size_t)rows * D_DIM;
            out[base + 0] = expf(v);
            out[base + 1] = mean;
            out[base + 2] = 0.25f * mean;
        }
    }
}

// ============================================================================
extern "C" void kernel_launch(void* const* d_in, const int* in_sizes, int n_in,
                              void* d_out, int out_size) {
    const float* inputs   = (const float*)d_in[0];
    const float* codebook = (const float*)d_in[1];
    float* out = (float*)d_out;
    int rows = in_sizes[0] / D_DIM;

    cudaFuncSetAttribute(k_main, cudaFuncAttributeMaxDynamicSharedMemorySize, SMEM_MAIN);

    k_init<<<1, 1024>>>();
    k_cnorm<<<K_CODES / 256, 256>>>(codebook);
    k_prep<<<dim3(K_CODES / 32, D_DIM / 32), dim3(32, 32)>>>(codebook);
    k_main<<<rows / BM, THREADS, SMEM_MAIN>>>(inputs, out);
    k_final<<<1, 1024>>>(out, rows);
}

// round 8
// speedup vs baseline: 2.6666x; 1.0090x over previous
#include <cuda_runtime.h>
#include <cuda_bf16.h>
#include <math.h>
#include <float.h>
#include <stdint.h>

// ============================================================================
// VectorQuantizer via warp-level bf16-split mma.sync + exact fp32 rescore.
// BM=64 rows/CTA, 256 threads (8 warps, 2m x 4n grid, warp tile 32x16),
// <=109KB smem -> 2 CTAs/SM for cross-CTA stall coverage.
// dist(n,k) = |x|^2 - 2 x.c + |c|^2 ; argmin over (cnorm[k] - 2*dot).
// dot = xh.ch + xh.cl + xl.ch (bf16 split, fp32 accum); top-2 + exact
// fp32 rescore when margin < EPS.
// out = [ste, perplexity, codebook_loss, commitment_loss]
// ============================================================================

#define D_DIM   256
#define K_CODES 1024
#define BM      64
#define BN      64
#define NCHUNK  (K_CODES / BN)        // 16
#define KS      64
#define NSLICES (NCHUNK * (D_DIM / KS))  // 64
#define THREADS 256
#define EPS_MARGIN 1e-2f

#define AST 264
#define BST 72

#define OFS_AH    0
#define ABYTES    (BM * AST * 2)                  // 33792
#define OFS_AL    (OFS_AH + ABYTES)
#define OFS_B     (OFS_AL + ABYTES)               // 67584
#define BBYTES    (BN * BST * 2)                  // 9216
#define OFS_REDV  (OFS_B + 4 * BBYTES)            // 104448
#define OFS_REDI  (OFS_REDV + BM * 4 * 4)
#define OFS_REDV2 (OFS_REDI + BM * 4 * 4)
#define OFS_REDI2 (OFS_REDV2 + BM * 4 * 4)
#define OFS_BK    (OFS_REDI2 + BM * 4 * 4)
#define SMEM_MAIN (OFS_BK + BM * 4)               // 108800

__device__ float          g_cT[K_CODES * D_DIM];
__device__ __nv_bfloat16  g_cbh[K_CODES * D_DIM];
__device__ __nv_bfloat16  g_cbl[K_CODES * D_DIM];
__device__ float          g_cnorm[K_CODES];
__device__ int            g_counts[K_CODES];
__device__ float          g_sumsq;

// ---------------------------------------------------------------------------
__device__ __forceinline__ uint32_t smem_u32(const void* p) {
    uint32_t a;
    asm("{ .reg .u64 t; cvta.to.shared.u64 t, %1; cvt.u32.u64 %0, t; }"
        : "=r"(a) : "l"(p));
    return a;
}

#define CP16(sa, ga) \
    asm volatile("cp.async.cg.shared.global [%0], [%1], 16;" \
                 :: "r"(sa), "l"(ga) : "memory")
#define CP_COMMIT() asm volatile("cp.async.commit_group;" ::: "memory")
#define CP_WAIT1()  asm volatile("cp.async.wait_group 1;" ::: "memory")

__device__ __forceinline__ void ldmx4(uint32_t& r0, uint32_t& r1,
                                      uint32_t& r2, uint32_t& r3, uint32_t a) {
    asm volatile("ldmatrix.sync.aligned.m8n8.x4.shared.b16 {%0,%1,%2,%3}, [%4];"
                 : "=r"(r0), "=r"(r1), "=r"(r2), "=r"(r3) : "r"(a));
}

#define MMA_BF16(c, a, b)                                                     \
    asm volatile("mma.sync.aligned.m16n8k16.row.col.f32.bf16.bf16.f32 "       \
                 "{%0,%1,%2,%3}, {%4,%5,%6,%7}, {%8,%9}, {%0,%1,%2,%3};"      \
                 : "+f"((c)[0]), "+f"((c)[1]), "+f"((c)[2]), "+f"((c)[3])     \
                 : "r"((a)[0]), "r"((a)[1]), "r"((a)[2]), "r"((a)[3]),        \
                   "r"((b)[0]), "r"((b)[1]))

// ============================================================================
__global__ void k_init() {
    int t = threadIdx.x;
    if (t < K_CODES) g_counts[t] = 0;
    if (t == 0) g_sumsq = 0.0f;
}

__global__ void k_cnorm(const float* __restrict__ cb) {
    int k = blockIdx.x * blockDim.x + threadIdx.x;
    float s = 0.0f;
    #pragma unroll 8
    for (int d = 0; d < D_DIM; d++) {
        float v = cb[d * K_CODES + k];
        s += v * v;
    }
    g_cnorm[k] = s;
}

__global__ void k_prep(const float* __restrict__ cb) {
    __shared__ float t[32][33];
    int k = blockIdx.x * 32 + threadIdx.x;
    int d = blockIdx.y * 32 + threadIdx.y;
    t[threadIdx.y][threadIdx.x] = cb[d * K_CODES + k];
    __syncthreads();
    int ko = blockIdx.x * 32 + threadIdx.y;
    int dd = blockIdx.y * 32 + threadIdx.x;
    float v = t[threadIdx.x][threadIdx.y];
    size_t o = (size_t)ko * D_DIM + dd;
    g_cT[o] = v;
    __nv_bfloat16 h = __float2bfloat16(v);
    g_cbh[o] = h;
    g_cbl[o] = __float2bfloat16(v - __bfloat162float(h));
}

// ============================================================================
// 256 threads: warp grid 2 (m) x 4 (n); warp tile 32 rows x 16 codes.
// ============================================================================
__global__ __launch_bounds__(THREADS, 2)
void k_main(const float* __restrict__ inputs, float* __restrict__ out) {
    extern __shared__ char smem[];
    const uint32_t sb = smem_u32(smem);
    const int tid    = threadIdx.x;
    const int wid    = tid >> 5;
    const int lane   = tid & 31;
    const int warp_m = wid & 1;          // 0..1 (32-row groups)
    const int warp_n = wid >> 1;         // 0..3 (16-code groups)
    const int g      = lane >> 2;
    const int t2     = lane & 3;
    const int rowBase = blockIdx.x * BM;

    float* s_redv  = (float*)(smem + OFS_REDV);
    int*   s_redi  = (int*)(smem + OFS_REDI);
    float* s_redv2 = (float*)(smem + OFS_REDV2);
    int*   s_redi2 = (int*)(smem + OFS_REDI2);
    int*   s_bk    = (int*)(smem + OFS_BK);

    // ---- A conversion: 64x256 fp32 -> bf16 hi/lo in smem ----
    {
        const float4* in4 = (const float4*)(inputs + (size_t)rowBase * D_DIM);
        #pragma unroll
        for (int i = 0; i < 16; i++) {
            int idx = tid + i * THREADS;      // 0..4095
            int r = idx >> 6;
            int d = (idx & 63) << 2;
            float4 v = in4[idx];
            __nv_bfloat16 h0 = __float2bfloat16(v.x);
            __nv_bfloat16 h1 = __float2bfloat16(v.y);
            __nv_bfloat16 h2 = __float2bfloat16(v.z);
            __nv_bfloat16 h3 = __float2bfloat16(v.w);
            __nv_bfloat16 l0 = __float2bfloat16(v.x - __bfloat162float(h0));
            __nv_bfloat16 l1 = __float2bfloat16(v.y - __bfloat162float(h1));
            __nv_bfloat16 l2 = __float2bfloat16(v.z - __bfloat162float(h2));
            __nv_bfloat16 l3 = __float2bfloat16(v.w - __bfloat162float(h3));
            uint64_t ph = (uint64_t)__bfloat16_as_ushort(h0)
                        | ((uint64_t)__bfloat16_as_ushort(h1) << 16)
                        | ((uint64_t)__bfloat16_as_ushort(h2) << 32)
                        | ((uint64_t)__bfloat16_as_ushort(h3) << 48);
            uint64_t pl = (uint64_t)__bfloat16_as_ushort(l0)
                        | ((uint64_t)__bfloat16_as_ushort(l1) << 16)
                        | ((uint64_t)__bfloat16_as_ushort(l2) << 32)
                        | ((uint64_t)__bfloat16_as_ushort(l3) << 48);
            uint32_t boff = (uint32_t)(r * AST + d) * 2;
            *(uint64_t*)(smem + OFS_AH + boff) = ph;
            *(uint64_t*)(smem + OFS_AL + boff) = pl;
        }
    }

    // slice s: chunk = s>>2, ds = s&3; fill buffer (s&1) with 64 codes x 64 d
    auto fill = [&](int s, int buf) {
        int chunk = s >> 2, ds = s & 3;
        const char* srcH = (const char*)(g_cbh + (size_t)(chunk * BN) * D_DIM + ds * KS);
        const char* srcL = (const char*)(g_cbl + (size_t)(chunk * BN) * D_DIM + ds * KS);
        uint32_t dstH = sb + OFS_B + buf * 2 * BBYTES;
        uint32_t dstL = dstH + BBYTES;
        #pragma unroll
        for (int i = 0; i < 2; i++) {
            int t = tid + i * THREADS;        // 0..511
            int code = t >> 3, seg = t & 7;
            uint32_t so = (uint32_t)(code * BST * 2 + seg * 16);
            size_t   go = (size_t)code * (D_DIM * 2) + seg * 16;
            CP16(dstH + so, srcH + go);
            CP16(dstL + so, srcL + go);
        }
    };
    fill(0, 0);
    CP_COMMIT();

    const int laneRowA = (lane & 7) + ((lane >> 3) & 1) * 8;
    const int laneColA = ((lane >> 4) & 1) * 8;
    const int laneRowB = (lane & 7) + ((lane >> 4) & 1) * 8;
    const int laneColB = ((lane >> 3) & 1) * 8;

    float acc[2][2][4];
    #pragma unroll
    for (int mt = 0; mt < 2; mt++)
        #pragma unroll
        for (int nt = 0; nt < 2; nt++)
            #pragma unroll
            for (int e = 0; e < 4; e++) acc[mt][nt][e] = 0.0f;

    // top-2 per row-slot b (4 slots: mt*2 + e_hi)
    float v1[4], v2[4];
    int   k1[4], k2[4];
    #pragma unroll
    for (int b = 0; b < 4; b++) {
        v1[b] = FLT_MAX; v2[b] = FLT_MAX; k1[b] = 0x7FFFFFFF; k2[b] = 0x7FFFFFFF;
    }

    for (int s = 0; s < NSLICES; s++) {
        if (s < NSLICES - 1) fill(s + 1, (s + 1) & 1);
        CP_COMMIT();
        CP_WAIT1();
        __syncthreads();

        const int ds  = s & 3;
        const int buf = s & 1;
        const uint32_t bH = sb + OFS_B + buf * 2 * BBYTES;

        #pragma unroll
        for (int kstep = 0; kstep < 4; kstep++) {
            const int ka = ds * KS + kstep * 16;
            const int kb = kstep * 16;

            uint32_t ah[2][4], al[2][4], bh[2][2], bl[2][2];
            {
                uint32_t addr = bH + (uint32_t)((warp_n * 16 + laneRowB) * BST
                                                + kb + laneColB) * 2;
                ldmx4(bh[0][0], bh[0][1], bh[1][0], bh[1][1], addr);
                addr += BBYTES;
                ldmx4(bl[0][0], bl[0][1], bl[1][0], bl[1][1], addr);
            }
            #pragma unroll
            for (int mt = 0; mt < 2; mt++) {
                uint32_t ro = (uint32_t)((warp_m * 32 + mt * 16 + laneRowA) * AST
                                         + ka + laneColA) * 2;
                ldmx4(ah[mt][0], ah[mt][1], ah[mt][2], ah[mt][3], sb + OFS_AH + ro);
                ldmx4(al[mt][0], al[mt][1], al[mt][2], al[mt][3], sb + OFS_AL + ro);
            }
            #pragma unroll
            for (int mt = 0; mt < 2; mt++)
                #pragma unroll
                for (int nt = 0; nt < 2; nt++) {
                    MMA_BF16(acc[mt][nt], ah[mt], bh[nt]);
                    MMA_BF16(acc[mt][nt], ah[mt], bl[nt]);
                    MMA_BF16(acc[mt][nt], al[mt], bh[nt]);
                }
        }

        if ((s & 3) == 3) {
            const int chunk = s >> 2;
            #pragma unroll
            for (int mt = 0; mt < 2; mt++)
                #pragma unroll
                for (int nt = 0; nt < 2; nt++)
                    #pragma unroll
                    for (int e = 0; e < 4; e++) {
                        int k = chunk * BN + warp_n * 16 + nt * 8 + t2 * 2 + (e & 1);
                        float dist = fmaf(-2.0f, acc[mt][nt][e], __ldg(g_cnorm + k));
                        int b = mt * 2 + (e >> 1);
                        if (dist < v1[b] || (dist == v1[b] && k < k1[b])) {
                            v2[b] = v1[b]; k2[b] = k1[b];
                            v1[b] = dist;  k1[b] = k;
                        } else if (dist < v2[b]) {
                            v2[b] = dist; k2[b] = k;
                        }
                        acc[mt][nt][e] = 0.0f;
                    }
        }
        __syncthreads();
    }

    // ---- top-2 merge across t2 lanes ----
    #pragma unroll
    for (int b = 0; b < 4; b++) {
        #pragma unroll
        for (int off = 1; off <= 2; off <<= 1) {
            float ov1 = __shfl_xor_sync(0xFFFFFFFFu, v1[b], off);
            int   ok1 = __shfl_xor_sync(0xFFFFFFFFu, k1[b], off);
            float ov2 = __shfl_xor_sync(0xFFFFFFFFu, v2[b], off);
            int   ok2 = __shfl_xor_sync(0xFFFFFFFFu, k2[b], off);
            float w1, lv; int j1, lk;
            if (ov1 < v1[b] || (ov1 == v1[b] && ok1 < k1[b])) {
                w1 = ov1; j1 = ok1; lv = v1[b]; lk = k1[b];
            } else {
                w1 = v1[b]; j1 = k1[b]; lv = ov1; lk = ok1;
            }
            float w2 = lv; int j2 = lk;
            if (v2[b] < w2) { w2 = v2[b]; j2 = k2[b]; }
            if (ov2  < w2) { w2 = ov2;  j2 = ok2;  }
            v1[b] = w1; k1[b] = j1; v2[b] = w2; k2[b] = j2;
        }
    }
    if (t2 == 0) {
        #pragma unroll
        for (int b = 0; b < 4; b++) {
            int mt = b >> 1, hi = b & 1;
            int row = warp_m * 32 + mt * 16 + g + hi * 8;
            s_redv[row * 4 + warp_n]  = v1[b];
            s_redi[row * 4 + warp_n]  = k1[b];
            s_redv2[row * 4 + warp_n] = v2[b];
            s_redi2[row * 4 + warp_n] = k2[b];
        }
    }
    __syncthreads();

    // ---- per-row final merge + exact rescore if margin small ----
    if (tid < BM) {
        float bv1 = s_redv[tid * 4], bv2 = s_redv2[tid * 4];
        int   bk1 = s_redi[tid * 4], bk2 = s_redi2[tid * 4];
        #pragma unroll
        for (int w = 1; w < 4; w++) {
            float ov1 = s_redv[tid * 4 + w],  ov2 = s_redv2[tid * 4 + w];
            int   ok1 = s_redi[tid * 4 + w],  ok2 = s_redi2[tid * 4 + w];
            float w1, lv; int j1, lk;
            if (ov1 < bv1 || (ov1 == bv1 && ok1 < bk1)) {
                w1 = ov1; j1 = ok1; lv = bv1; lk = bk1;
            } else {
                w1 = bv1; j1 = bk1; lv = ov1; lk = ok1;
            }
            float w2 = lv; int j2 = lk;
            if (bv2 < w2) { w2 = bv2; j2 = bk2; }
            if (ov2 < w2) { w2 = ov2; j2 = ok2; }
            bv1 = w1; bk1 = j1; bv2 = w2; bk2 = j2;
        }
        int bk = bk1;
        if (bv2 - bv1 < EPS_MARGIN) {
            const float* xr = inputs + (size_t)(rowBase + tid) * D_DIM;
            const float* c1 = g_cT + (size_t)bk1 * D_DIM;
            const float* c2 = g_cT + (size_t)bk2 * D_DIM;
            float d1 = 0.0f, d2 = 0.0f;
            for (int d = 0; d < D_DIM; d++) {
                float x = __ldg(xr + d);
                d1 = fmaf(x, __ldg(c1 + d), d1);
                d2 = fmaf(x, __ldg(c2 + d), d2);
            }
            float e1 = fmaf(-2.0f, d1, __ldg(g_cnorm + bk1));
            float e2 = fmaf(-2.0f, d2, __ldg(g_cnorm + bk2));
            if (e2 < e1 || (e2 == e1 && bk2 < bk1)) bk = bk2;
        }
        s_bk[tid] = bk;
        atomicAdd(&g_counts[bk], 1);
    }
    __syncthreads();

    // ---- epilogue: ste + sum (q-x)^2, exact fp32 x from gmem ----
    {
        float ss = 0.0f;
        #pragma unroll
        for (int rr = 0; rr < 8; rr++) {
            const int r = wid * 8 + rr;
            const int bk = s_bk[r];
            const float4* x4 = (const float4*)(inputs + (size_t)(rowBase + r) * D_DIM);
            const float4* q4 = (const float4*)(g_cT + (size_t)bk * D_DIM);
            float4* o4 = (float4*)(out + (size_t)(rowBase + r) * D_DIM);
            #pragma unroll
            for (int h = 0; h < 2; h++) {
                int d4 = lane + h * 32;
                float4 x = x4[d4];
                float4 q = q4[d4];
                float d0 = q.x - x.x, d1 = q.y - x.y, d2 = q.z - x.z, d3 = q.w - x.w;
                float4 o;
                o.x = x.x + d0; o.y = x.y + d1; o.z = x.z + d2; o.w = x.w + d3;
                o4[d4] = o;
                ss = fmaf(d0, d0, ss); ss = fmaf(d1, d1, ss);
                ss = fmaf(d2, d2, ss); ss = fmaf(d3, d3, ss);
            }
        }
        #pragma unroll
        for (int o = 16; o; o >>= 1)
            ss += __shfl_xor_sync(0xFFFFFFFFu, ss, o);
        if (lane == 0) atomicAdd(&g_sumsq, ss);
    }
}

// ============================================================================
__global__ void k_final(float* __restrict__ out, int rows) {
    __shared__ float red[32];
    int tid = threadIdx.x;
    float p = (float)g_counts[tid] / (float)rows;
    float term = -p * logf(p + 1e-10f);
    #pragma unroll
    for (int o = 16; o; o >>= 1)
        term += __shfl_xor_sync(0xFFFFFFFFu, term, o);
    if ((tid & 31) == 0) red[tid >> 5] = term;
    __syncthreads();
    if (tid < 32) {
        float v = red[tid];
        #pragma unroll
        for (int o = 16; o; o >>= 1)
            v += __shfl_xor_sync(0xFFFFFFFFu, v, o);
        if (tid == 0) {
            float mean = g_sumsq / ((float)rows * (float)D_DIM);
            size_t base = (size_t)rows * D_DIM;
            out[base + 0] = expf(v);
            out[base + 1] = mean;
            out[base + 2] = 0.25f * mean;
        }
    }
}

// ============================================================================
extern "C" void kernel_launch(void* const* d_in, const int* in_sizes, int n_in,
                              void* d_out, int out_size) {
    const float* inputs   = (const float*)d_in[0];
    const float* codebook = (const float*)d_in[1];
    float* out = (float*)d_out;
    int rows = in_sizes[0] / D_DIM;

    cudaFuncSetAttribute(k_main, cudaFuncAttributeMaxDynamicSharedMemorySize, SMEM_MAIN);

    k_init<<<1, 1024>>>();
    k_cnorm<<<K_CODES / 256, 256>>>(codebook);
    k_prep<<<dim3(K_CODES / 32, D_DIM / 32), dim3(32, 32)>>>(codebook);
    k_main<<<rows / BM, THREADS, SMEM_MAIN>>>(inputs, out);
    k_final<<<1, 1024>>>(out, rows);
}